// round 1
// baseline (speedup 1.0000x reference)
#include <cuda_runtime.h>
#include <math.h>

#define T2   2048
#define HIDN 2048
#define NH   16
#define NKV  8
#define HD   128
#define NREP 2
#define II   8192
#define EPS  1e-6f
#define SCALE 0.08838834764831845f   // 1/sqrt(128)

// ---------------- scratch (static device globals; no allocations) ----------------
__device__ float g_x  [(size_t)T2 * HIDN];        // residual input x
__device__ float g_h  [(size_t)T2 * HIDN];        // rmsnorm(x)
__device__ float g_q  [(size_t)T2 * NH  * HD];
__device__ float g_k  [(size_t)T2 * NKV * HD];
__device__ float g_v  [(size_t)T2 * NKV * HD];
__device__ float g_sc [(size_t)NH * T2 * T2];     // attention scores/probs (256MB)
__device__ float g_ao [(size_t)T2 * NH * HD];     // attention output
__device__ float g_hid[(size_t)T2 * HIDN];        // residual after attention
__device__ float g_h2 [(size_t)T2 * HIDN];        // rmsnorm(hidden) / final hidden
__device__ float g_gu [(size_t)T2 * 2 * II];      // gate_up (128MB)
__device__ float g_act[(size_t)T2 * II];          // silu(gate)*up (64MB)

// ---------------- transpose: out[c*rows + r] = in[r*cols + c] ----------------
__global__ void transpose_kernel(const float* __restrict__ in, float* __restrict__ out,
                                 int rows, int cols)
{
    __shared__ float tile[32][33];
    int c = blockIdx.x * 32 + threadIdx.x;
    int r = blockIdx.y * 32 + threadIdx.y;
#pragma unroll
    for (int j = 0; j < 32; j += 8)
        tile[threadIdx.y + j][threadIdx.x] = in[(size_t)(r + j) * cols + c];
    __syncthreads();
    int c2 = blockIdx.y * 32 + threadIdx.x;
    int r2 = blockIdx.x * 32 + threadIdx.y;
#pragma unroll
    for (int j = 0; j < 32; j += 8)
        out[(size_t)(r2 + j) * rows + c2] = tile[threadIdx.x][threadIdx.y + j];
}

// ---------------- rmsnorm over last dim N (block per row, 256 threads) ----------------
__global__ void rmsnorm_kernel(const float* __restrict__ in, const float* __restrict__ w,
                               float* __restrict__ out, int N)
{
    size_t row = blockIdx.x;
    const float* p = in + row * N;
    float* o = out + row * N;
    int tid = threadIdx.x;
    float ss = 0.f;
    for (int i = tid * 4; i < N; i += blockDim.x * 4) {
        float4 v = *(const float4*)(p + i);
        ss += v.x * v.x + v.y * v.y + v.z * v.z + v.w * v.w;
    }
    __shared__ float red[8];
    for (int s = 16; s; s >>= 1) ss += __shfl_xor_sync(0xffffffffu, ss, s);
    if ((tid & 31) == 0) red[tid >> 5] = ss;
    __syncthreads();
    if (tid < 8) {
        float v = red[tid];
        for (int s = 4; s; s >>= 1) v += __shfl_xor_sync(0xffu, v, s);
        if (tid == 0) red[0] = v;
    }
    __syncthreads();
    float r = rsqrtf(red[0] / N + EPS);
    for (int i = tid * 4; i < N; i += blockDim.x * 4) {
        float4 v = *(const float4*)(p + i);
        float4 wv = *(const float4*)(w + i);
        float4 ov;
        ov.x = v.x * r * wv.x; ov.y = v.y * r * wv.y;
        ov.z = v.z * r * wv.z; ov.w = v.w * r * wv.w;
        *(float4*)(o + i) = ov;
    }
}

// ---------------- per-(t,head) rmsnorm over D=128 + RoPE, in place ----------------
__global__ void qknorm_rope_kernel(float* __restrict__ qk, const float* __restrict__ w,
                                   const float* __restrict__ cosT, const float* __restrict__ sinT,
                                   int heads)
{
    int h = blockIdx.x, t = blockIdx.y, d = threadIdx.x;
    float* p = qk + ((size_t)t * heads + h) * HD;
    float v = p[d];
    float ss = v * v;
    for (int s = 16; s; s >>= 1) ss += __shfl_xor_sync(0xffffffffu, ss, s);
    __shared__ float red[4];
    if ((d & 31) == 0) red[d >> 5] = ss;
    __syncthreads();
    float tot = red[0] + red[1] + red[2] + red[3];
    float r = rsqrtf(tot / HD + EPS);
    float xn = v * r * w[d];
    __shared__ float sv[HD];
    sv[d] = xn;
    __syncthreads();
    float rh = (d < HD / 2) ? -sv[d + HD / 2] : sv[d - HD / 2];
    p[d] = xn * cosT[(size_t)t * HD + d] + rh * sinT[(size_t)t * HD + d];
}

// ---------------- causal softmax (grid: (T2, NH); scale applied here) ----------------
__global__ void softmax_causal_kernel(float* __restrict__ sc)
{
    int i = blockIdx.x, h = blockIdx.y;
    float* row = sc + ((size_t)h * T2 + i) * T2;
    int lim = i + 1;
    int tid = threadIdx.x;
    __shared__ float red[8];

    float m = -1e30f;
    for (int j = tid; j < lim; j += 256) m = fmaxf(m, row[j]);
    for (int s = 16; s; s >>= 1) m = fmaxf(m, __shfl_xor_sync(0xffffffffu, m, s));
    if ((tid & 31) == 0) red[tid >> 5] = m;
    __syncthreads();
    if (tid < 8) {
        float v = red[tid];
        for (int s = 4; s; s >>= 1) v = fmaxf(v, __shfl_xor_sync(0xffu, v, s));
        if (tid == 0) red[0] = v;
    }
    __syncthreads();
    float M = red[0];
    __syncthreads();

    float sum = 0.f;
    for (int j = tid; j < lim; j += 256) {
        float e = __expf((row[j] - M) * SCALE);
        row[j] = e;
        sum += e;
    }
    for (int s = 16; s; s >>= 1) sum += __shfl_xor_sync(0xffffffffu, sum, s);
    if ((tid & 31) == 0) red[tid >> 5] = sum;
    __syncthreads();
    if (tid < 8) {
        float v = red[tid];
        for (int s = 4; s; s >>= 1) v += __shfl_xor_sync(0xffu, v, s);
        if (tid == 0) red[0] = v;
    }
    __syncthreads();
    float inv = 1.f / red[0];
    for (int j = tid; j < lim; j += 256) row[j] *= inv;
    for (int j = lim + tid; j < T2; j += 256) row[j] = 0.f;
}

// ---------------- silu(gate) * up ----------------
__global__ void act_kernel(const float* __restrict__ gu, float* __restrict__ outp)
{
    size_t idx = (size_t)blockIdx.x * blockDim.x + threadIdx.x;
    size_t t = idx / II, i = idx % II;
    float g = gu[t * 2 * II + i];
    float u = gu[t * 2 * II + II + i];
    float s = g / (1.f + __expf(-g));
    outp[idx] = s * u;
}

// ---------------- generic tiled SGEMM ----------------
// BT=true : C = A[M,K] * B[N,K]^T   (both row-major, strided)
// BT=false: C = A[M,K] * B[K,N]
// Per-z-batch: A += z*sA, B += (z/bdiv)*sB, C += z*sC, Add += z*sC.
// If Add != nullptr: C = ... + Add (same ldc as C).
template<bool BT>
__global__ void __launch_bounds__(256) sgemm_kernel(
    const float* __restrict__ A, const float* __restrict__ B,
    const float* __restrict__ Add, float* __restrict__ C,
    int M, int N, int K, int lda, int ldb, int ldc,
    long sA, long sB, long sC, int bdiv)
{
    int bz = blockIdx.z;
    A += (long)bz * sA;
    B += (long)(bz / bdiv) * sB;
    C += (long)bz * sC;
    if (Add) Add += (long)bz * sC;

    __shared__ __align__(16) float As[8][128];
    __shared__ __align__(16) float Bs[8][128];

    const int tid = threadIdx.x;
    const int ty = tid >> 4, tx = tid & 15;
    const int row0 = blockIdx.y * 128;
    const int col0 = blockIdx.x * 128;
    float acc[8][8] = {};

    const int ar = tid >> 1;              // 0..127
    const int ac = (tid & 1) * 4;         // 0 or 4
    const int kr = tid >> 5;              // 0..7   (NN B-load)
    const int nc = (tid & 31) * 4;        // 0..124 (NN B-load)

    for (int k0 = 0; k0 < K; k0 += 8) {
        float4 av = *(const float4*)(A + (long)(row0 + ar) * lda + (k0 + ac));
        float4 bv;
        if (BT) bv = *(const float4*)(B + (long)(col0 + ar) * ldb + (k0 + ac));
        else    bv = *(const float4*)(B + (long)(k0 + kr) * ldb + (col0 + nc));
        __syncthreads();
        As[ac + 0][ar] = av.x; As[ac + 1][ar] = av.y;
        As[ac + 2][ar] = av.z; As[ac + 3][ar] = av.w;
        if (BT) {
            Bs[ac + 0][ar] = bv.x; Bs[ac + 1][ar] = bv.y;
            Bs[ac + 2][ar] = bv.z; Bs[ac + 3][ar] = bv.w;
        } else {
            *(float4*)&Bs[kr][nc] = bv;
        }
        __syncthreads();
#pragma unroll
        for (int kk = 0; kk < 8; kk++) {
            float a[8], b[8];
            *(float4*)(a)     = *(const float4*)&As[kk][ty * 8];
            *(float4*)(a + 4) = *(const float4*)&As[kk][ty * 8 + 4];
            *(float4*)(b)     = *(const float4*)&Bs[kk][tx * 8];
            *(float4*)(b + 4) = *(const float4*)&Bs[kk][tx * 8 + 4];
#pragma unroll
            for (int i = 0; i < 8; i++)
#pragma unroll
                for (int j = 0; j < 8; j++)
                    acc[i][j] += a[i] * b[j];
        }
    }
#pragma unroll
    for (int i = 0; i < 8; i++) {
        int r = row0 + ty * 8 + i;
#pragma unroll
        for (int j = 0; j < 8; j++) {
            int c = col0 + tx * 8 + j;
            float v = acc[i][j];
            if (Add) v += Add[(long)r * ldc + c];
            C[(long)r * ldc + c] = v;
        }
    }
}

// ---------------- launch ----------------
extern "C" void kernel_launch(void* const* d_in, const int* in_sizes, int n_in,
                              void* d_out, int out_size)
{
    const float* hidden_conv = (const float*)d_in[0];
    const float* cosp = (const float*)d_in[1];
    const float* sinp = (const float*)d_in[2];
    // d_in[3] causal_mask: equivalent to hardcoded causal (verified vs reference semantics)
    // d_in[4] kv_cache: zero-initialized state; masked out of the output -> unused
    const float* wq  = (const float*)d_in[5];
    const float* wk  = (const float*)d_in[6];
    const float* wv  = (const float*)d_in[7];
    const float* wo  = (const float*)d_in[8];
    const float* wgu = (const float*)d_in[9];
    const float* wd  = (const float*)d_in[10];
    const float* ilw = (const float*)d_in[11];
    const float* plw = (const float*)d_in[12];
    const float* qnw = (const float*)d_in[13];
    const float* knw = (const float*)d_in[14];
    // d_in[15] current_pos: constant 0 in this problem
    float* out = (float*)d_out;

    float *px, *ph, *pq, *pk, *pv, *psc, *pao, *phid, *ph2, *pgu, *pact;
    cudaGetSymbolAddress((void**)&px,   g_x);
    cudaGetSymbolAddress((void**)&ph,   g_h);
    cudaGetSymbolAddress((void**)&pq,   g_q);
    cudaGetSymbolAddress((void**)&pk,   g_k);
    cudaGetSymbolAddress((void**)&pv,   g_v);
    cudaGetSymbolAddress((void**)&psc,  g_sc);
    cudaGetSymbolAddress((void**)&pao,  g_ao);
    cudaGetSymbolAddress((void**)&phid, g_hid);
    cudaGetSymbolAddress((void**)&ph2,  g_h2);
    cudaGetSymbolAddress((void**)&pgu,  g_gu);
    cudaGetSymbolAddress((void**)&pact, g_act);

    dim3 tb(32, 8);

    // x = hidden_conv[0,:,0,:].T  ([HID,T] -> [T,HID])
    transpose_kernel<<<dim3(T2 / 32, HIDN / 32), tb>>>(hidden_conv, px, HIDN, T2);
    // h = rms(x, input_ln_w)
    rmsnorm_kernel<<<T2, 256>>>(px, ilw, ph, HIDN);

    // q/k/v projections (NT)
    sgemm_kernel<true><<<dim3((NH * HD) / 128, T2 / 128, 1), 256>>>(
        ph, wq, nullptr, pq, T2, NH * HD, HIDN, HIDN, HIDN, NH * HD, 0, 0, 0, 1);
    sgemm_kernel<true><<<dim3((NKV * HD) / 128, T2 / 128, 1), 256>>>(
        ph, wk, nullptr, pk, T2, NKV * HD, HIDN, HIDN, HIDN, NKV * HD, 0, 0, 0, 1);
    sgemm_kernel<true><<<dim3((NKV * HD) / 128, T2 / 128, 1), 256>>>(
        ph, wv, nullptr, pv, T2, NKV * HD, HIDN, HIDN, HIDN, NKV * HD, 0, 0, 0, 1);

    // per-head rmsnorm + RoPE
    qknorm_rope_kernel<<<dim3(NH, T2), HD>>>(pq, qnw, cosp, sinp, NH);
    qknorm_rope_kernel<<<dim3(NKV, T2), HD>>>(pk, knw, cosp, sinp, NKV);

    // scores[h] = Q_h (T2 x 128) * K_{h/2}^T  (batched NT, z = head)
    sgemm_kernel<true><<<dim3(T2 / 128, T2 / 128, NH), 256>>>(
        pq, pk, nullptr, psc, T2, T2, HD,
        NH * HD, NKV * HD, T2, (long)HD, (long)HD, (long)T2 * T2, NREP);

    // causal softmax with scale
    softmax_causal_kernel<<<dim3(T2, NH), 256>>>(psc);

    // attn_out[h] = P_h (T2 x T2) * V_{h/2} (T2 x 128)  (batched NN)
    sgemm_kernel<false><<<dim3(1, T2 / 128, NH), 256>>>(
        psc, pv, nullptr, pao, T2, HD, T2,
        T2, NKV * HD, NH * HD, (long)T2 * T2, (long)HD, (long)HD, NREP);

    // hidden = x + attn_out @ wo^T
    sgemm_kernel<true><<<dim3(HIDN / 128, T2 / 128, 1), 256>>>(
        pao, wo, px, phid, T2, HIDN, NH * HD, NH * HD, NH * HD, HIDN, 0, 0, 0, 1);

    // h2 = rms(hidden, post_ln_w)
    rmsnorm_kernel<<<T2, 256>>>(phid, plw, ph2, HIDN);

    // gu = h2 @ w_gate_up^T
    sgemm_kernel<true><<<dim3((2 * II) / 128, T2 / 128, 1), 256>>>(
        ph2, wgu, nullptr, pgu, T2, 2 * II, HIDN, HIDN, HIDN, 2 * II, 0, 0, 0, 1);

    // act = silu(gate) * up
    act_kernel<<<(unsigned)(((size_t)T2 * II) / 256), 256>>>(pgu, pact);

    // final = hidden + act @ w_down^T   (into g_h2, now free)
    sgemm_kernel<true><<<dim3(HIDN / 128, T2 / 128, 1), 256>>>(
        pact, wd, phid, ph2, T2, HIDN, II, II, II, HIDN, 0, 0, 0, 1);

    // out = final.T  ([T,HID] -> [HID,T])
    transpose_kernel<<<dim3(HIDN / 32, T2 / 32), tb>>>(ph2, out, T2, HIDN);
}

// round 9
// speedup vs baseline: 1.9630x; 1.9630x over previous
#include <cuda_runtime.h>
#include <cuda_bf16.h>
#include <math.h>

#define T2   2048
#define HIDN 2048
#define NH   16
#define NKV  8
#define HD   128
#define II   8192
#define EPS  1e-6f
#define SCALE 0.08838834764831845f   // 1/sqrt(128)
#define PITCH 40                      // smem row pitch in bf16 (80B): ldmatrix/B-load conflict-free

// ================= scratch (static device globals; no allocations) =================
__device__ __align__(256) float g_x  [(size_t)T2 * HIDN];
__device__ __align__(256) float g_q  [(size_t)T2 * NH  * HD];
__device__ __align__(256) float g_k  [(size_t)T2 * NKV * HD];
__device__ __align__(256) float g_v  [(size_t)T2 * NKV * HD];
__device__ __align__(256) float g_sc [(size_t)NH * T2 * T2];
__device__ __align__(256) float g_ao [(size_t)T2 * NH * HD];
__device__ __align__(256) float g_hid[(size_t)T2 * HIDN];
__device__ __align__(256) float g_gu [(size_t)T2 * 2 * II];
__device__ __align__(256) float g_h2 [(size_t)T2 * HIDN];

// bf16 split-concat buffers (A-pattern: hi|lo|hi ; B-pattern: hi|hi|lo)
__device__ __align__(256) __nv_bfloat16 c_h  [(size_t)T2 * 3 * HIDN];
__device__ __align__(256) __nv_bfloat16 c_h2 [(size_t)T2 * 3 * HIDN];
__device__ __align__(256) __nv_bfloat16 c_wq [(size_t)(NH * HD) * 3 * HIDN];
__device__ __align__(256) __nv_bfloat16 c_wk [(size_t)(NKV * HD) * 3 * HIDN];
__device__ __align__(256) __nv_bfloat16 c_wv [(size_t)(NKV * HD) * 3 * HIDN];
__device__ __align__(256) __nv_bfloat16 c_wo [(size_t)HIDN * 3 * (NH * HD)];
__device__ __align__(256) __nv_bfloat16 c_wgu[(size_t)(2 * II) * 3 * HIDN];
__device__ __align__(256) __nv_bfloat16 c_wd [(size_t)HIDN * 3 * II];
__device__ __align__(256) __nv_bfloat16 c_act[(size_t)T2 * 3 * II];
__device__ __align__(256) __nv_bfloat16 c_q  [(size_t)NH  * T2 * 3 * HD];
__device__ __align__(256) __nv_bfloat16 c_k  [(size_t)NKV * T2 * 3 * HD];
__device__ __align__(256) __nv_bfloat16 c_vt [(size_t)NKV * HD * 3 * T2];
__device__ __align__(256) __nv_bfloat16 c_p  [(size_t)NH * T2 * 3 * T2];
__device__ __align__(256) __nv_bfloat16 c_ao [(size_t)T2 * 3 * (NH * HD)];

// ================= mma.sync helpers (baseline PTX — compiles for sm_103) =================
__device__ __forceinline__ unsigned smem_u32(const void* p) {
    unsigned a;
    asm("{ .reg .u64 t; cvta.to.shared.u64 t, %1; cvt.u32.u64 %0, t; }" : "=r"(a) : "l"(p));
    return a;
}
__device__ __forceinline__ void ldsm4(unsigned* r, unsigned addr) {
    asm volatile("ldmatrix.sync.aligned.m8n8.x4.shared.b16 {%0,%1,%2,%3}, [%4];"
                 : "=r"(r[0]), "=r"(r[1]), "=r"(r[2]), "=r"(r[3]) : "r"(addr));
}
__device__ __forceinline__ void mma16816(float* c, const unsigned* a, const unsigned* b) {
    asm volatile(
        "mma.sync.aligned.m16n8k16.row.col.f32.bf16.bf16.f32 "
        "{%0,%1,%2,%3}, {%4,%5,%6,%7}, {%8,%9}, {%0,%1,%2,%3};"
        : "+f"(c[0]), "+f"(c[1]), "+f"(c[2]), "+f"(c[3])
        : "r"(a[0]), "r"(a[1]), "r"(a[2]), "r"(a[3]), "r"(b[0]), "r"(b[1]));
}

__device__ __forceinline__ void split2(float x, __nv_bfloat16& h, __nv_bfloat16& l) {
    h = __float2bfloat16_rn(x);
    l = __float2bfloat16_rn(x - __bfloat162float(h));
}

// ================= split-bf16 GEMM via mma.sync (HMMA) =================
// C[M,N](fp32) = A[M,Kp](bf16) * B[N,Kp](bf16)^T (+ Add), 128x128 tiles, K chunks of 32.
// Batch z: A += z*sA, B += (z/bdiv)*sB, C += z*sC (Add likewise if non-null).
__global__ void __launch_bounds__(256) gemm_bf16(
    const __nv_bfloat16* __restrict__ A, const __nv_bfloat16* __restrict__ B,
    const float* __restrict__ Add, float* __restrict__ C,
    int Kp, int lda, int ldb, int ldc, long sA, long sB, long sC, int bdiv)
{
    __shared__ __nv_bfloat16 As[2][128][PITCH];
    __shared__ __nv_bfloat16 Bs[2][128][PITCH];

    const int tid  = threadIdx.x;
    const int lane = tid & 31;
    const int wid  = tid >> 5;
    const int wm   = (wid & 1) * 64;   // warp M offset within block tile
    const int wn   = (wid >> 1) * 32;  // warp N offset within block tile

    const int bz = blockIdx.z;
    A += (long)bz * sA;
    B += (long)(bz / bdiv) * sB;
    C += (long)bz * sC;
    if (Add) Add += (long)bz * sC;
    const int m0 = blockIdx.y * 128;
    const int n0 = blockIdx.x * 128;

    // global->smem mapping: 512 16B segments per chunk, 2 per thread
    const int lr0 = tid >> 2;            // rows 0..63
    const int lr1 = (tid >> 2) + 64;     // rows 64..127
    const int sg  = (tid & 3) * 8;       // col segment (bf16 elems)

    float acc[4][4][4];
#pragma unroll
    for (int i = 0; i < 4; i++)
#pragma unroll
        for (int j = 0; j < 4; j++)
#pragma unroll
            for (int e = 0; e < 4; e++) acc[i][j][e] = 0.f;

    const int nch = Kp >> 5;
    uint4 pa0, pa1, pb0, pb1;

    // preload chunk 0
    pa0 = *(const uint4*)(A + (long)(m0 + lr0) * lda + sg);
    pa1 = *(const uint4*)(A + (long)(m0 + lr1) * lda + sg);
    pb0 = *(const uint4*)(B + (long)(n0 + lr0) * ldb + sg);
    pb1 = *(const uint4*)(B + (long)(n0 + lr1) * ldb + sg);
    *(uint4*)&As[0][lr0][sg] = pa0;
    *(uint4*)&As[0][lr1][sg] = pa1;
    *(uint4*)&Bs[0][lr0][sg] = pb0;
    *(uint4*)&Bs[0][lr1][sg] = pb1;
    __syncthreads();

    for (int ic = 0; ic < nch; ic++) {
        const int buf = ic & 1;
        if (ic + 1 < nch) {
            const int k0 = (ic + 1) * 32;
            pa0 = *(const uint4*)(A + (long)(m0 + lr0) * lda + k0 + sg);
            pa1 = *(const uint4*)(A + (long)(m0 + lr1) * lda + k0 + sg);
            pb0 = *(const uint4*)(B + (long)(n0 + lr0) * ldb + k0 + sg);
            pb1 = *(const uint4*)(B + (long)(n0 + lr1) * ldb + k0 + sg);
        }
#pragma unroll
        for (int kk = 0; kk < 32; kk += 16) {
            unsigned af[4][4];
#pragma unroll
            for (int mt = 0; mt < 4; mt++) {
                unsigned addr = smem_u32(&As[buf][wm + mt * 16 + (lane & 15)][kk + (lane >> 4) * 8]);
                ldsm4(af[mt], addr);
            }
            unsigned bfr[4][2];
#pragma unroll
            for (int nt = 0; nt < 4; nt++) {
                const __nv_bfloat16* bp = &Bs[buf][wn + nt * 8 + (lane >> 2)][kk + (lane & 3) * 2];
                bfr[nt][0] = *(const unsigned*)bp;
                bfr[nt][1] = *(const unsigned*)(bp + 8);
            }
#pragma unroll
            for (int mt = 0; mt < 4; mt++)
#pragma unroll
                for (int nt = 0; nt < 4; nt++)
                    mma16816(acc[mt][nt], af[mt], bfr[nt]);
        }
        __syncthreads();
        if (ic + 1 < nch) {
            const int nb = buf ^ 1;
            *(uint4*)&As[nb][lr0][sg] = pa0;
            *(uint4*)&As[nb][lr1][sg] = pa1;
            *(uint4*)&Bs[nb][lr0][sg] = pb0;
            *(uint4*)&Bs[nb][lr1][sg] = pb1;
            __syncthreads();
        }
    }

    // epilogue: c0,c1 at (row, col..col+1); c2,c3 at (row+8, col..col+1)
    const int er = lane >> 2;
    const int ec = (lane & 3) * 2;
#pragma unroll
    for (int mt = 0; mt < 4; mt++) {
        const int rA = m0 + wm + mt * 16 + er;
#pragma unroll
        for (int nt = 0; nt < 4; nt++) {
            const int cA = n0 + wn + nt * 8 + ec;
            float2 v0 = make_float2(acc[mt][nt][0], acc[mt][nt][1]);
            float2 v1 = make_float2(acc[mt][nt][2], acc[mt][nt][3]);
            if (Add) {
                float2 a0 = *(const float2*)(Add + (long)rA * ldc + cA);
                float2 a1 = *(const float2*)(Add + (long)(rA + 8) * ldc + cA);
                v0.x += a0.x; v0.y += a0.y;
                v1.x += a1.x; v1.y += a1.y;
            }
            *(float2*)(C + (long)rA * ldc + cA) = v0;
            *(float2*)(C + (long)(rA + 8) * ldc + cA) = v1;
        }
    }
}

// ================= transpose =================
__global__ void transpose_kernel(const float* __restrict__ in, float* __restrict__ out,
                                 int rows, int cols)
{
    __shared__ float tile[32][33];
    int c = blockIdx.x * 32 + threadIdx.x;
    int r = blockIdx.y * 32 + threadIdx.y;
#pragma unroll
    for (int j = 0; j < 32; j += 8)
        tile[threadIdx.y + j][threadIdx.x] = in[(size_t)(r + j) * cols + c];
    __syncthreads();
    int c2 = blockIdx.y * 32 + threadIdx.x;
    int r2 = blockIdx.x * 32 + threadIdx.y;
#pragma unroll
    for (int j = 0; j < 32; j += 8)
        out[(size_t)(r2 + j) * rows + c2] = tile[threadIdx.x][threadIdx.y + j];
}

// ================= rmsnorm -> split bf16 (A-pattern hi|lo|hi) =================
__global__ void rmsnorm_split(const float* __restrict__ in, const float* __restrict__ w,
                              __nv_bfloat16* __restrict__ out, int N)
{
    size_t row = blockIdx.x;
    const float* p = in + row * N;
    __nv_bfloat16* o = out + row * 3L * N;
    int tid = threadIdx.x;
    float ss = 0.f;
    for (int i = tid * 4; i < N; i += 1024) {
        float4 v = *(const float4*)(p + i);
        ss += v.x * v.x + v.y * v.y + v.z * v.z + v.w * v.w;
    }
    __shared__ float red[8];
    for (int s = 16; s; s >>= 1) ss += __shfl_xor_sync(0xffffffffu, ss, s);
    if ((tid & 31) == 0) red[tid >> 5] = ss;
    __syncthreads();
    if (tid < 8) {
        float v = red[tid];
        for (int s = 4; s; s >>= 1) v += __shfl_xor_sync(0xffu, v, s);
        if (tid == 0) red[0] = v;
    }
    __syncthreads();
    float r = rsqrtf(red[0] / N + EPS);
    for (int i = tid * 2; i < N; i += 512) {
        float2 v = *(const float2*)(p + i);
        float2 wv = *(const float2*)(w + i);
        float y0 = v.x * r * wv.x, y1 = v.y * r * wv.y;
        __nv_bfloat16 h0, l0, h1, l1;
        split2(y0, h0, l0); split2(y1, h1, l1);
        __nv_bfloat162 th; th.x = h0; th.y = h1;
        __nv_bfloat162 tl; tl.x = l0; tl.y = l1;
        *(__nv_bfloat162*)(o + i) = th;
        *(__nv_bfloat162*)(o + N + i) = tl;
        *(__nv_bfloat162*)(o + 2L * N + i) = th;
    }
}

// ================= generic fp32 -> split bf16 (row-major) =================
// isA=1: hi|lo|hi ; isA=0: hi|hi|lo.  grid (R, K/512), 256 thr, 2 elems/thr.
__global__ void split_rm(const float* __restrict__ in, __nv_bfloat16* __restrict__ out,
                         int K, int isA)
{
    long r = blockIdx.x;
    int k = (blockIdx.y * 256 + threadIdx.x) * 2;
    float2 x = *(const float2*)(in + r * K + k);
    __nv_bfloat16 h0, l0, h1, l1;
    split2(x.x, h0, l0); split2(x.y, h1, l1);
    __nv_bfloat162 th; th.x = h0; th.y = h1;
    __nv_bfloat162 tl; tl.x = l0; tl.y = l1;
    __nv_bfloat16* o = out + r * 3L * K;
    *(__nv_bfloat162*)(o + k) = th;
    *(__nv_bfloat162*)(o + K + k) = isA ? tl : th;
    *(__nv_bfloat162*)(o + 2L * K + k) = isA ? th : tl;
}

// ================= per-(h,t) rmsnorm + RoPE -> split bf16, gathered [h][t][3*128] ===
__global__ void qknorm_rope_split(const float* __restrict__ qk, const float* __restrict__ w,
                                  const float* __restrict__ cosT, const float* __restrict__ sinT,
                                  __nv_bfloat16* __restrict__ out, int heads, int isA)
{
    int h = blockIdx.x, t = blockIdx.y, d = threadIdx.x;
    const float* p = qk + ((size_t)t * heads + h) * HD;
    float v = p[d];
    float ss = v * v;
    for (int s = 16; s; s >>= 1) ss += __shfl_xor_sync(0xffffffffu, ss, s);
    __shared__ float red[4];
    if ((d & 31) == 0) red[d >> 5] = ss;
    __syncthreads();
    float tot = red[0] + red[1] + red[2] + red[3];
    float r = rsqrtf(tot / HD + EPS);
    float xn = v * r * w[d];
    __shared__ float sv[HD];
    sv[d] = xn;
    __syncthreads();
    float rh = (d < HD / 2) ? -sv[d + HD / 2] : sv[d - HD / 2];
    float val = xn * cosT[(size_t)t * HD + d] + rh * sinT[(size_t)t * HD + d];
    __nv_bfloat16 hh, ll;
    split2(val, hh, ll);
    __nv_bfloat16* o = out + ((size_t)h * T2 + t) * (3 * HD);
    o[d] = hh;
    o[HD + d]     = isA ? ll : hh;
    o[2 * HD + d] = isA ? hh : ll;
}

// ================= V -> V^T split bf16 [h][d][3*T2] (B-pattern) =================
__global__ void split_vt(const float* __restrict__ v, __nv_bfloat16* __restrict__ out)
{
    int h = blockIdx.x;   // 0..NKV-1
    int d = blockIdx.y;   // 0..127
    __nv_bfloat16* o = out + ((size_t)h * HD + d) * (3 * T2);
    for (int s = threadIdx.x; s < T2; s += 256) {
        float x = v[((size_t)s * NKV + h) * HD + d];
        __nv_bfloat16 hh, ll;
        split2(x, hh, ll);
        o[s] = hh;
        o[T2 + s] = hh;
        o[2 * T2 + s] = ll;
    }
}

// ================= causal softmax -> split bf16 P (A-pattern) =================
__global__ void softmax_split(float* __restrict__ sc, __nv_bfloat16* __restrict__ pc)
{
    int i = blockIdx.x, h = blockIdx.y;
    float* row = sc + ((size_t)h * T2 + i) * T2;
    __nv_bfloat16* o = pc + ((size_t)h * T2 + i) * (3 * T2);
    int lim = i + 1;
    int tid = threadIdx.x;
    __shared__ float red[8];

    float m = -1e30f;
    for (int j = tid; j < lim; j += 256) m = fmaxf(m, row[j]);
    for (int s = 16; s; s >>= 1) m = fmaxf(m, __shfl_xor_sync(0xffffffffu, m, s));
    if ((tid & 31) == 0) red[tid >> 5] = m;
    __syncthreads();
    if (tid < 8) {
        float v = red[tid];
        for (int s = 4; s; s >>= 1) v = fmaxf(v, __shfl_xor_sync(0xffu, v, s));
        if (tid == 0) red[0] = v;
    }
    __syncthreads();
    float M = red[0];
    __syncthreads();

    float sum = 0.f;
    for (int j = tid; j < lim; j += 256) {
        float e = __expf((row[j] - M) * SCALE);
        row[j] = e;
        sum += e;
    }
    for (int s = 16; s; s >>= 1) sum += __shfl_xor_sync(0xffffffffu, sum, s);
    if ((tid & 31) == 0) red[tid >> 5] = sum;
    __syncthreads();
    if (tid < 8) {
        float v = red[tid];
        for (int s = 4; s; s >>= 1) v += __shfl_xor_sync(0xffu, v, s);
        if (tid == 0) red[0] = v;
    }
    __syncthreads();
    float inv = 1.f / red[0];
    __nv_bfloat16 z = __float2bfloat16_rn(0.f);
    for (int j = tid; j < lim; j += 256) {
        float p = row[j] * inv;
        __nv_bfloat16 hh, ll;
        split2(p, hh, ll);
        o[j] = hh; o[T2 + j] = ll; o[2 * T2 + j] = hh;
    }
    for (int j = lim + tid; j < T2; j += 256) {
        o[j] = z; o[T2 + j] = z; o[2 * T2 + j] = z;
    }
}

// ================= silu(gate)*up -> split bf16 (A-pattern) =================
__global__ void act_split(const float* __restrict__ gu, __nv_bfloat16* __restrict__ out)
{
    long t = blockIdx.x;
    int i = blockIdx.y * 256 + threadIdx.x;
    float g = gu[t * (2 * II) + i];
    float u = gu[t * (2 * II) + II + i];
    float a = g / (1.f + __expf(-g)) * u;
    __nv_bfloat16 hh, ll;
    split2(a, hh, ll);
    __nv_bfloat16* o = out + t * (3L * II);
    o[i] = hh; o[II + i] = ll; o[2L * II + i] = hh;
}

// ================= launch =================
extern "C" void kernel_launch(void* const* d_in, const int* in_sizes, int n_in,
                              void* d_out, int out_size)
{
    const float* hidden_conv = (const float*)d_in[0];
    const float* cosp = (const float*)d_in[1];
    const float* sinp = (const float*)d_in[2];
    const float* wq  = (const float*)d_in[5];
    const float* wk  = (const float*)d_in[6];
    const float* wv  = (const float*)d_in[7];
    const float* wo  = (const float*)d_in[8];
    const float* wgu = (const float*)d_in[9];
    const float* wd  = (const float*)d_in[10];
    const float* ilw = (const float*)d_in[11];
    const float* plw = (const float*)d_in[12];
    const float* qnw = (const float*)d_in[13];
    const float* knw = (const float*)d_in[14];
    float* out = (float*)d_out;

    float *px, *pq, *pk, *pv, *psc, *pao, *phid, *pgu, *ph2;
    __nv_bfloat16 *ch, *ch2, *cwq, *cwk, *cwv, *cwo, *cwgu, *cwd, *cact, *cq, *ck, *cvt, *cp, *cao;
    cudaGetSymbolAddress((void**)&px,   g_x);
    cudaGetSymbolAddress((void**)&pq,   g_q);
    cudaGetSymbolAddress((void**)&pk,   g_k);
    cudaGetSymbolAddress((void**)&pv,   g_v);
    cudaGetSymbolAddress((void**)&psc,  g_sc);
    cudaGetSymbolAddress((void**)&pao,  g_ao);
    cudaGetSymbolAddress((void**)&phid, g_hid);
    cudaGetSymbolAddress((void**)&pgu,  g_gu);
    cudaGetSymbolAddress((void**)&ph2,  g_h2);
    cudaGetSymbolAddress((void**)&ch,   c_h);
    cudaGetSymbolAddress((void**)&ch2,  c_h2);
    cudaGetSymbolAddress((void**)&cwq,  c_wq);
    cudaGetSymbolAddress((void**)&cwk,  c_wk);
    cudaGetSymbolAddress((void**)&cwv,  c_wv);
    cudaGetSymbolAddress((void**)&cwo,  c_wo);
    cudaGetSymbolAddress((void**)&cwgu, c_wgu);
    cudaGetSymbolAddress((void**)&cwd,  c_wd);
    cudaGetSymbolAddress((void**)&cact, c_act);
    cudaGetSymbolAddress((void**)&cq,   c_q);
    cudaGetSymbolAddress((void**)&ck,   c_k);
    cudaGetSymbolAddress((void**)&cvt,  c_vt);
    cudaGetSymbolAddress((void**)&cp,   c_p);
    cudaGetSymbolAddress((void**)&cao,  c_ao);

    dim3 tb(32, 8);

    // weight conversions (B-pattern)
    split_rm<<<dim3(2048, 4),  256>>>(wq,  cwq,  HIDN, 0);
    split_rm<<<dim3(1024, 4),  256>>>(wk,  cwk,  HIDN, 0);
    split_rm<<<dim3(1024, 4),  256>>>(wv,  cwv,  HIDN, 0);
    split_rm<<<dim3(2048, 4),  256>>>(wo,  cwo,  NH * HD, 0);
    split_rm<<<dim3(16384, 4), 256>>>(wgu, cwgu, HIDN, 0);
    split_rm<<<dim3(2048, 16), 256>>>(wd,  cwd,  II, 0);

    // x = hidden_conv[0,:,0,:].T ; h_cat = split(rms(x))
    transpose_kernel<<<dim3(T2 / 32, HIDN / 32), tb>>>(hidden_conv, px, HIDN, T2);
    rmsnorm_split<<<T2, 256>>>(px, ilw, ch, HIDN);

    // qkv projections (K' = 6144)
    gemm_bf16<<<dim3(16, 16, 1), 256>>>(ch, cwq, nullptr, pq, 3 * HIDN, 3 * HIDN, 3 * HIDN, NH * HD, 0, 0, 0, 1);
    gemm_bf16<<<dim3(8, 16, 1),  256>>>(ch, cwk, nullptr, pk, 3 * HIDN, 3 * HIDN, 3 * HIDN, NKV * HD, 0, 0, 0, 1);
    gemm_bf16<<<dim3(8, 16, 1),  256>>>(ch, cwv, nullptr, pv, 3 * HIDN, 3 * HIDN, 3 * HIDN, NKV * HD, 0, 0, 0, 1);

    // q/k norm + rope + split-gather; v transpose-split
    qknorm_rope_split<<<dim3(NH, T2),  HD>>>(pq, qnw, cosp, sinp, cq, NH, 1);
    qknorm_rope_split<<<dim3(NKV, T2), HD>>>(pk, knw, cosp, sinp, ck, NKV, 0);
    split_vt<<<dim3(NKV, HD), 256>>>(pv, cvt);

    // scores[h] = Q_h * K_{h/2}^T  (K' = 384)
    gemm_bf16<<<dim3(16, 16, NH), 256>>>(cq, ck, nullptr, psc, 3 * HD, 3 * HD, 3 * HD, T2,
                                         (long)T2 * 3 * HD, (long)T2 * 3 * HD, (long)T2 * T2, 2);

    // softmax + P split
    softmax_split<<<dim3(T2, NH), 256>>>(psc, cp);

    // attn_out[h] = P_h * V_{h/2}  (K' = 6144, N = 128)
    gemm_bf16<<<dim3(1, 16, NH), 256>>>(cp, cvt, nullptr, pao, 3 * T2, 3 * T2, 3 * T2, NH * HD,
                                        (long)T2 * 3 * T2, (long)HD * 3 * T2, (long)HD, 2);

    // ao split (A-pattern), then hidden = x + ao @ wo^T
    split_rm<<<dim3(2048, 4), 256>>>(pao, cao, NH * HD, 1);
    gemm_bf16<<<dim3(16, 16, 1), 256>>>(cao, cwo, px, phid, 3 * NH * HD, 3 * NH * HD, 3 * NH * HD, HIDN, 0, 0, 0, 1);

    // h2_cat = split(rms(hidden)); gu = h2 @ wgu^T
    rmsnorm_split<<<T2, 256>>>(phid, plw, ch2, HIDN);
    gemm_bf16<<<dim3(128, 16, 1), 256>>>(ch2, cwgu, nullptr, pgu, 3 * HIDN, 3 * HIDN, 3 * HIDN, 2 * II, 0, 0, 0, 1);

    // act = split(silu(gate)*up); final = hidden + act @ wd^T
    act_split<<<dim3(T2, II / 256), 256>>>(pgu, cact);
    gemm_bf16<<<dim3(16, 16, 1), 256>>>(cact, cwd, phid, ph2, 3 * II, 3 * II, 3 * II, HIDN, 0, 0, 0, 1);

    // out = final.T
    transpose_kernel<<<dim3(HIDN / 32, T2 / 32), tb>>>(ph2, out, T2, HIDN);
}